// round 11
// baseline (speedup 1.0000x reference)
#include <cuda_runtime.h>
#include <cstdint>
#include <cstddef>

typedef unsigned long long ull;

#define KD    9
#define PADV  4
#define BATCH 2
#define CCH   64
#define HH    32
#define WW    32
#define DD    32
#define TW    4
#define NTHR  288          // 9 dx * 4 wl * 8 dbk -> 9 warps, all active

#define CCHUNK 4
#define NCHUNK (CCH / CCHUNK)   // 16
#define NBUF   3

// smem (floats):
//   in1 tile: [c][w][d]     stride 36 (32 data + 4 pad), all 64 ch resident, LDS.128-aligned
//   in2 halo: 3 buffers of [cc][row][d'] stride 44 (4 zero | 32 | 4 zero | 4 pad), 4-ch chunk
#define IN1_STRIDE 36
#define IN1_FLOATS (CCH*TW*IN1_STRIDE)              // 9216   (36864 B)
#define IN2_ROWS   12
#define IN2_STRIDE 44
#define IN2_BUF    (CCHUNK*IN2_ROWS*IN2_STRIDE)     // 2112   (8448 B)
#define IN2_FLOATS (NBUF*IN2_BUF)                   // 6336
#define SMEM_BYTES ((IN1_FLOATS + IN2_FLOATS)*4)    // 62208 B -> 3 CTAs/SM

#define STAGE_V4 (CCHUNK*IN2_ROWS*8)                // 384 float4 per chunk

__device__ __forceinline__ ull pack2f(float lo, float hi) {
    ull r;
    asm("mov.b64 %0, {%1, %2};" : "=l"(r) : "f"(lo), "f"(hi));
    return r;
}
// packed f32x2 FMA: d = a*b + d  (FFMA2; only reachable via PTX)
__device__ __forceinline__ void ffma2(ull& d, ull a, ull b) {
    asm("fma.rn.f32x2 %0, %1, %2, %0;" : "+l"(d) : "l"(a), "l"(b));
}
__device__ __forceinline__ unsigned su32(const void* p) {
    return (unsigned)__cvta_generic_to_shared(p);
}
#define CP16(s, g)   asm volatile("cp.async.cg.shared.global [%0], [%1], 16;" :: "r"(s), "l"(g))
#define CP_COMMIT()  asm volatile("cp.async.commit_group;")
#define CP_WAIT1()   asm volatile("cp.async.wait_group 1;")
#define CP_WAIT0()   asm volatile("cp.async.wait_group 0;")

__global__ void __launch_bounds__(NTHR, 3)
corr3d_kernel(const float* __restrict__ in1, const float* __restrict__ in2,
              float* __restrict__ out)
{
    extern __shared__ float sm[];
    float* s1 = sm;               // in1 tile (all 64 channels)
    float* s2 = sm + IN1_FLOATS;  // in2 halo: three 4-channel buffers

    const int tid = threadIdx.x;
    const int w0  = blockIdx.x * TW;
    const int h   = blockIdx.y;
    const int b   = blockIdx.z;

    // Zero all in2 buffers once: d-edge pads and OOB-w rows stay zero forever
    // (every restage rewrites exactly the same valid-cell pattern).
    for (int i = tid; i < IN2_FLOATS; i += NTHR) s2[i] = 0.0f;

    // Stage full in1 tile: 64c x 4w x 8 float4
    for (int i = tid; i < CCH*TW*8; i += NTHR) {
        int j  = i & 7;
        int rw = i >> 3;
        int c  = rw >> 2;
        int w  = rw & 3;
        const float4 v = *reinterpret_cast<const float4*>(
            in1 + ((((size_t)b*CCH + c)*HH + h)*WW + (w0 + w))*DD + j*4);
        *reinterpret_cast<float4*>(s1 + (c*TW + w)*IN1_STRIDE + j*4) = v;
    }
    __syncthreads();   // zero-fill + in1 visible before any cp.async lands

    // thread mapping: tid = dx*32 + wl*8 + dbk  (warp == dx)
    const int dx  = tid >> 5;        // 0..8
    const int wl  = (tid >> 3) & 3;  // 0..3
    const int dbk = tid & 7;         // 0..7
    const int d0  = dbk << 2;        // 0,4,...,28
    const int row = wl + dx;         // in2 halo row index 0..11

    const float* in2b = in2 + ((size_t)b*CCH)*HH*WW*DD;

    // per-thread staging geometry (chunk/dy invariant); 384 v4 over 288 thr -> k<2
    int  st_sm[2];  bool st_ok[2];  int st_g[2];
    #pragma unroll
    for (int k = 0; k < 2; ++k) {
        int i = tid + k*NTHR;
        if (i < STAGE_V4) {
            int j  = i & 7;
            int rr = i >> 3;
            int cl = rr / IN2_ROWS;
            int r  = rr - cl*IN2_ROWS;
            int wp = w0 + r - PADV;
            st_ok[k] = ((unsigned)wp < (unsigned)WW);
            st_sm[k] = (cl*IN2_ROWS + r)*IN2_STRIDE + 4 + j*4;
            st_g[k]  = cl*(HH*WW*DD) + wp*DD + j*4;     // + hp*WW*DD + c0*HWD
        } else { st_ok[k] = false; st_sm[k] = 0; st_g[k] = 0; }
    }

    for (int dy = 0; dy < KD; ++dy) {
        ull acc[KD][2];
        #pragma unroll
        for (int z = 0; z < KD; ++z) { acc[z][0] = 0ULL; acc[z][1] = 0ULL; }

        const int hp = h + dy - PADV;           // uniform across block
        if ((unsigned)hp < (unsigned)HH) {
            const float* gbase = in2b + (size_t)hp*(WW*DD);

            // prologue: prefetch chunks 0 and 1
            #pragma unroll
            for (int pc = 0; pc < 2; ++pc) {
                float* buf = s2 + pc*IN2_BUF;
                const float* g = gbase + (size_t)(pc*CCHUNK)*(HH*WW*DD);
                #pragma unroll
                for (int k = 0; k < 2; ++k)
                    if (st_ok[k]) CP16(su32(buf + st_sm[k]), g + st_g[k]);
                CP_COMMIT();
            }

            int bi = 0;                          // buffer index of chunk ck
            for (int ck = 0; ck < NCHUNK; ++ck) {
                if (ck < NCHUNK - 1) CP_WAIT1(); else CP_WAIT0();  // chunk ck landed
                __syncthreads();   // all warps' data visible; compute(ck-1) finished

                // prefetch chunk ck+2 into the buffer freed by compute(ck-1)
                if (ck + 2 < NCHUNK) {
                    int b2 = bi + 2; if (b2 >= NBUF) b2 -= NBUF;
                    float* buf2 = s2 + b2*IN2_BUF;
                    const float* g = gbase + (size_t)((ck + 2)*CCHUNK)*(HH*WW*DD);
                    #pragma unroll
                    for (int k = 0; k < 2; ++k)
                        if (st_ok[k]) CP16(su32(buf2 + st_sm[k]), g + st_g[k]);
                    CP_COMMIT();
                }

                // compute chunk ck
                const ull* p1 = reinterpret_cast<const ull*>(s1)
                                + ((ck*CCHUNK)*TW + wl)*(IN1_STRIDE/2) + (d0 >> 1);
                const ull* p2 = reinterpret_cast<const ull*>(s2 + bi*IN2_BUF)
                                + row*(IN2_STRIDE/2) + (d0 >> 1);
                #pragma unroll 1
                for (int c = 0; c < CCHUNK; ++c) {
                    // V[0..5]: in2 floats [d0 .. d0+11]; A: in1 floats [d0..d0+3]
                    ull V[6], A[2];
                    {
                        ulonglong2 t0 = *reinterpret_cast<const ulonglong2*>(p2);
                        ulonglong2 t1 = *reinterpret_cast<const ulonglong2*>(p2 + 2);
                        ulonglong2 t2 = *reinterpret_cast<const ulonglong2*>(p2 + 4);
                        V[0]=t0.x; V[1]=t0.y; V[2]=t1.x; V[3]=t1.y; V[4]=t2.x; V[5]=t2.y;
                        ulonglong2 ta = *reinterpret_cast<const ulonglong2*>(p1);
                        A[0]=ta.x; A[1]=ta.y;
                    }
                    #pragma unroll
                    for (int j = 0; j < 2; ++j) {
                        #pragma unroll
                        for (int dz = 0; dz < KD; dz += 2)
                            ffma2(acc[dz][j], V[j + (dz >> 1)], A[j]);
                        #pragma unroll
                        for (int dz = 1; dz < KD; dz += 2) {
                            int m = j + ((dz - 1) >> 1);
                            ull ov = pack2f(
                                __uint_as_float((unsigned)(V[m]   >> 32)),
                                __uint_as_float((unsigned)(V[m+1] & 0xFFFFFFFFu)));
                            ffma2(acc[dz][j], ov, A[j]);
                        }
                    }
                    p1 += TW * (IN1_STRIDE/2);        // 72 ull per channel
                    p2 += IN2_ROWS * (IN2_STRIDE/2);  // 264 ull per channel
                }

                if (++bi == NBUF) bi = 0;
            }
            __syncthreads();   // protect buffers before next dy's prologue writes
        }
        // write (zeros if hp was out of range — output buffer is poisoned)
        {
            const int kbase = (dy*KD + dx)*KD;
            float* op = out + (((size_t)b*(KD*KD*KD) + kbase)*HH + h)*(WW*DD)
                            + (w0 + wl)*DD + d0;
            #pragma unroll
            for (int dz = 0; dz < KD; ++dz) {
                ulonglong2 v0; v0.x = acc[dz][0]; v0.y = acc[dz][1];
                *reinterpret_cast<ulonglong2*>(op) = v0;     // 16B store, aligned
                op += (size_t)HH * WW * DD;                  // next dz channel
            }
        }
    }
}

extern "C" void kernel_launch(void* const* d_in, const int* in_sizes, int n_in,
                              void* d_out, int out_size)
{
    const float* in1 = (const float*)d_in[0];
    const float* in2 = (const float*)d_in[1];
    float* out = (float*)d_out;

    cudaFuncSetAttribute(corr3d_kernel,
                         cudaFuncAttributeMaxDynamicSharedMemorySize, SMEM_BYTES);

    dim3 grid(WW / TW, HH, BATCH);   // 8 x 32 x 2 = 512 blocks
    corr3d_kernel<<<grid, NTHR, SMEM_BYTES>>>(in1, in2, out);
}

// round 12
// speedup vs baseline: 2.3501x; 2.3501x over previous
#include <cuda_runtime.h>
#include <cstdint>
#include <cstddef>

typedef unsigned long long ull;

#define KD    9
#define PADV  4
#define BATCH 2
#define CCH   64
#define HH    32
#define WW    32
#define DD    32
#define TW    4
#define NTHR  288          // 9 dx * 4 wl * 8 dbk -> 9 warps, all active

#define CCHUNK 16
#define NCHUNK (CCH / CCHUNK)   // 4

// smem (floats):
//   in1 tile: [c][w][d]     stride 36 (32 data + 4 pad), all 64 ch resident, LDS.128-aligned
//   in2 halo: [cc][row][d'] stride 44 (4 zero | 32 data | 4 zero | 4 pad), 16-ch chunk
#define IN1_STRIDE 36
#define IN1_FLOATS (CCH*TW*IN1_STRIDE)              // 9216   (36864 B)
#define IN2_ROWS   12
#define IN2_STRIDE 44
#define IN2_FLOATS (CCHUNK*IN2_ROWS*IN2_STRIDE)     // 8448   (33792 B)
#define SMEM_BYTES ((IN1_FLOATS + IN2_FLOATS)*4)    // 70656 B -> 3 CTAs/SM (212 KB < 228 KB)

__device__ __forceinline__ ull pack2f(float lo, float hi) {
    ull r;
    asm("mov.b64 %0, {%1, %2};" : "=l"(r) : "f"(lo), "f"(hi));
    return r;
}
// packed f32x2 FMA: d = a*b + d  (FFMA2; only reachable via PTX)
__device__ __forceinline__ void ffma2(ull& d, ull a, ull b) {
    asm("fma.rn.f32x2 %0, %1, %2, %0;" : "+l"(d) : "l"(a), "l"(b));
}

__global__ void __launch_bounds__(NTHR, 3)
corr3d_kernel(const float* __restrict__ in1, const float* __restrict__ in2,
              float* __restrict__ out)
{
    extern __shared__ float sm[];
    float* s1 = sm;               // in1 tile (all 64 channels)
    float* s2 = sm + IN1_FLOATS;  // in2 halo rows (one 16-channel chunk)

    const int tid = threadIdx.x;
    const int w0  = blockIdx.x * TW;
    const int h   = blockIdx.y;
    const int b   = blockIdx.z & 1;        // z = dy*2 + b
    const int dy  = blockIdx.z >> 1;

    // thread mapping: tid = dx*32 + wl*8 + dbk  (warp == dx)
    const int dx  = tid >> 5;        // 0..8
    const int wl  = (tid >> 3) & 3;  // 0..3
    const int dbk = tid & 7;         // 0..7
    const int d0  = dbk << 2;        // 0,4,...,28
    const int row = wl + dx;         // in2 halo row index 0..11

    ull acc[KD][2];
    #pragma unroll
    for (int z = 0; z < KD; ++z) { acc[z][0] = 0ULL; acc[z][1] = 0ULL; }

    const int hp = h + dy - PADV;    // uniform across block
    if ((unsigned)hp < (unsigned)HH) {
        // Zero in2 buffer: d-edge pads and OOB-w rows stay zero across restages
        // (every restage rewrites exactly the same valid-cell pattern).
        for (int i = tid; i < IN2_FLOATS; i += NTHR) s2[i] = 0.0f;

        // Stage full in1 tile: 64c x 4w x 8 float4
        #pragma unroll 1
        for (int i = tid; i < CCH*TW*8; i += NTHR) {
            int j  = i & 7;
            int rw = i >> 3;
            int c  = rw >> 2;
            int w  = rw & 3;
            const float4 v = *reinterpret_cast<const float4*>(
                in1 + ((((size_t)b*CCH + c)*HH + h)*WW + (w0 + w))*DD + j*4);
            *reinterpret_cast<float4*>(s1 + (c*TW + w)*IN1_STRIDE + j*4) = v;
        }

        const float* in2b = in2 + ((size_t)b*CCH)*HH*WW*DD;

        for (int ck = 0; ck < NCHUNK; ++ck) {
            const int c0 = ck * CCHUNK;
            __syncthreads();   // prev compute (or init/in1-stage) done before restage

            // Stage 16 channels x 12 in2 rows at h'=hp  (1536 float4)
            #pragma unroll 1
            for (int i = tid; i < CCHUNK*IN2_ROWS*8; i += NTHR) {
                int j  = i & 7;
                int rr = i >> 3;
                int cl = rr / IN2_ROWS;
                int r  = rr - cl*IN2_ROWS;
                int wp = w0 + r - PADV;
                if ((unsigned)wp < (unsigned)WW) {
                    const float4 v = *reinterpret_cast<const float4*>(
                        in2b + ((size_t)(c0 + cl))*(HH*WW*DD) + (hp*WW + wp)*DD + j*4);
                    *reinterpret_cast<float4*>(
                        s2 + (cl*IN2_ROWS + r)*IN2_STRIDE + 4 + j*4) = v;
                }
            }
            __syncthreads();

            const ull* p1 = reinterpret_cast<const ull*>(s1)
                            + (c0*TW + wl)*(IN1_STRIDE/2) + (d0 >> 1);
            const ull* p2 = reinterpret_cast<const ull*>(s2)
                            + row*(IN2_STRIDE/2) + (d0 >> 1);
            #pragma unroll 1
            for (int c = 0; c < CCHUNK; ++c) {
                // V[0..5]: in2 floats [d0 .. d0+11]; A: in1 floats [d0..d0+3]
                ull V[6], A[2];
                {
                    ulonglong2 t0 = *reinterpret_cast<const ulonglong2*>(p2);
                    ulonglong2 t1 = *reinterpret_cast<const ulonglong2*>(p2 + 2);
                    ulonglong2 t2 = *reinterpret_cast<const ulonglong2*>(p2 + 4);
                    V[0]=t0.x; V[1]=t0.y; V[2]=t1.x; V[3]=t1.y; V[4]=t2.x; V[5]=t2.y;
                    ulonglong2 ta = *reinterpret_cast<const ulonglong2*>(p1);
                    A[0]=ta.x; A[1]=ta.y;
                }
                #pragma unroll
                for (int j = 0; j < 2; ++j) {
                    // even dz: aligned pairs straight from V
                    #pragma unroll
                    for (int dz = 0; dz < KD; dz += 2)
                        ffma2(acc[dz][j], V[j + (dz >> 1)], A[j]);
                    // odd dz: odd-aligned pair built on the fly
                    #pragma unroll
                    for (int dz = 1; dz < KD; dz += 2) {
                        int m = j + ((dz - 1) >> 1);
                        ull ov = pack2f(
                            __uint_as_float((unsigned)(V[m]   >> 32)),
                            __uint_as_float((unsigned)(V[m+1] & 0xFFFFFFFFu)));
                        ffma2(acc[dz][j], ov, A[j]);
                    }
                }
                p1 += TW * (IN1_STRIDE/2);        // 72 ull per channel
                p2 += IN2_ROWS * (IN2_STRIDE/2);  // 264 ull per channel
            }
        }
    }

    // write (zeros if hp was out of range — output buffer is poisoned)
    {
        const int kbase = (dy*KD + dx)*KD;
        float* op = out + (((size_t)b*(KD*KD*KD) + kbase)*HH + h)*(WW*DD)
                        + (w0 + wl)*DD + d0;
        #pragma unroll
        for (int dz = 0; dz < KD; ++dz) {
            ulonglong2 v0; v0.x = acc[dz][0]; v0.y = acc[dz][1];
            *reinterpret_cast<ulonglong2*>(op) = v0;     // 16B store, aligned
            op += (size_t)HH * WW * DD;                  // next dz channel
        }
    }
}

extern "C" void kernel_launch(void* const* d_in, const int* in_sizes, int n_in,
                              void* d_out, int out_size)
{
    const float* in1 = (const float*)d_in[0];
    const float* in2 = (const float*)d_in[1];
    float* out = (float*)d_out;

    cudaFuncSetAttribute(corr3d_kernel,
                         cudaFuncAttributeMaxDynamicSharedMemorySize, SMEM_BYTES);

    dim3 grid(WW / TW, HH, BATCH * KD);   // 8 x 32 x 18 = 4608 blocks, z = dy*2 + b
    corr3d_kernel<<<grid, NTHR, SMEM_BYTES>>>(in1, in2, out);
}